// round 16
// baseline (speedup 1.0000x reference)
#include <cuda_runtime.h>
#include <cuda_bf16.h>

#define NXv 432
#define NYv 496
#define CAPV (NXv * NYv)            // 214272 (NZ=1)
#define MAXP 100
#define NPTS_MAX 300000
#define NB 210                      // ceil(CAPV / 1024)
#define HOTS 8                      // hot slots per voxel (L2-resident table)

// ---- scratch (zero-init at load; k_place tail restores the invariant that
// g_count / g_look are all-zero on entry). Slot tables / g_voxid need no
// cleaning: reads are always bounded by / gated on this call's data. ----
__device__ int g_count[CAPV];
__device__ int g_slotsA[CAPV * HOTS];         // hot slots: 6.9 MB -> L2-resident
__device__ int g_slotsB[CAPV * (MAXP - HOTS)];// cold overflow: ~0 traffic in practice
__device__ int g_voxid[CAPV];                 // packed: compactRow*256 + min(cnt,255)
__device__ unsigned long long g_look[NB];     // decoupled-lookback words

// Pack: bits[0:20)=occ prefix, bits[62:64)=status (1=AGG, 2=PREFIX)
__device__ __forceinline__ unsigned long long packLB(int st, int o) {
    return ((unsigned long long)st << 62) | (unsigned long long)(o & 0xFFFFF);
}

// Shared binning math. NUMERICS LOCKED (R7): XLA rewrites /const into
// *reciprocal(const); fp32(1/0.16f)=6.25f exactly. Returns -1 if invalid.
__device__ __forceinline__ int bin_lin(float4 p) {
    bool valid = (p.x >= 0.0f)    && (p.x < 69.12f) &&
                 (p.y >= -39.68f) && (p.y < 39.68f) &&
                 (p.z >= -3.0f)   && (p.z < 1.0f);
    if (!valid) return -1;
    float qx = __fmul_rn(__fsub_rn(p.x,   0.0f),  6.25f);
    float qy = __fmul_rn(__fsub_rn(p.y, -39.68f), 6.25f);
    int vx = min(max((int)floorf(qx), 0), NXv - 1);
    int vy = min(max((int)floorf(qy), 0), NYv - 1);
    return vy * NXv + vx;             // vz always 0 (NZ=1; z-range validated)
}

// ---------------------------------------------------------------
// K_fillc: write -1.0f over the coords slice only (memset covers the zeros;
// -1.0f = 0xBF800000 is not a uniform byte pattern, so it needs a kernel).
__global__ void k_fillc(float4* __restrict__ coords4, int m4) {
    int i = blockIdx.x * blockDim.x + threadIdx.x;
    if (i < m4) coords4[i] = make_float4(-1.0f, -1.0f, -1.0f, -1.0f);
}

// K_bin: binning + fused slot scatter (arrival slot free from the counting
// atomic). 2 points per thread for load ILP.
__global__ void k_bin(const float4* __restrict__ pts, int n) {
    int i0 = blockIdx.x * (blockDim.x * 2) + threadIdx.x;
#pragma unroll
    for (int k = 0; k < 2; k++) {
        int i = i0 + k * 256;
        if (i >= n) continue;
        int lin = bin_lin(pts[i]);
        if (lin < 0) continue;
        int slot = atomicAdd(&g_count[lin], 1);
        if (slot < HOTS)      g_slotsA[lin * HOTS + slot] = i;
        else if (slot < MAXP) g_slotsB[lin * (MAXP - HOTS) + slot - HOTS] = i;
    }
}

// K_scan: single-pass decoupled-lookback scan of the occupied flag. Packs
// {compactRow, cnt} per occupied lin, and writes coords + counts DIRECTLY to
// the output (memset/fillc have already laid down the padding).
__global__ void k_scan(float* __restrict__ out, int hasCoords, int hasCounts) {
    const long long voxFloats   = (long long)CAPV * MAXP * 4;
    const long long coordFloats = (long long)CAPV * 3;
    __shared__ int wO[8];
    __shared__ int sExc;
    int b = blockIdx.x, t = threadIdx.x;
    int lane = t & 31, warp = t >> 5;
    int e0 = b * 1024 + t * 4;
    int occ[4], cnt[4];
    int so = 0;
#pragma unroll
    for (int j = 0; j < 4; j++) {
        int e = e0 + j;
        int c = (e < CAPV) ? g_count[e] : 0;
        cnt[j] = c;
        occ[j] = (c > 0) ? 1 : 0;
        so += occ[j];
    }
    int io = so;
#pragma unroll
    for (int off = 1; off < 32; off <<= 1) {
        int vo = __shfl_up_sync(0xFFFFFFFFu, io, off);
        if (lane >= off) io += vo;
    }
    if (lane == 31) wO[warp] = io;
    __syncthreads();
    if (warp == 0 && lane < 8) {
        int a = wO[lane];
#pragma unroll
        for (int off = 1; off < 8; off <<= 1) {
            int va = __shfl_up_sync(0xFFu, a, off);
            if (lane >= off) a += va;
        }
        wO[lane] = a;
    }
    __syncthreads();
    int blkO = wO[7];

    // ---- decoupled lookback (warp 0) ----
    if (t < 32) {
        if (lane == 0 && b > 0)
            *(volatile unsigned long long*)(g_look + b) = packLB(1, blkO);
        int accO = 0;
        if (b > 0) {
            int end = b;
            for (;;) {
                int idx = end - 1 - lane;
                unsigned long long v = 0;
                if (idx >= 0) {
                    volatile unsigned long long* vp = g_look + idx;
                    do { v = *vp; } while ((v >> 62) == 0ull);
                }
                bool isPref = (idx >= 0) && ((v >> 62) == 2ull);
                unsigned pm = __ballot_sync(0xFFFFFFFFu, isPref);
                int o = (idx >= 0) ? (int)(v & 0xFFFFF) : 0;
                if (pm) {
                    int fp = __ffs(pm) - 1;
                    if (lane > fp) o = 0;
                }
#pragma unroll
                for (int off = 16; off; off >>= 1)
                    o += __shfl_down_sync(0xFFFFFFFFu, o, off);
                if (lane == 0) accO += o;
                if (pm) break;
                end -= 32;
            }
        }
        if (lane == 0) {
            sExc = accO;
            *(volatile unsigned long long*)(g_look + b) = packLB(2, accO + blkO);
        }
    }
    __syncthreads();

    int exO = sExc + (warp ? wO[warp - 1] : 0) + (io - so);
#pragma unroll
    for (int j = 0; j < 4; j++) {
        int e = e0 + j;
        if (e < CAPV && cnt[j] > 0) {
            int vox = exO;
            int cpk = (cnt[j] < 255) ? cnt[j] : 255;
            g_voxid[e] = vox * 256 + cpk;
            if (hasCoords) {
                int y = e / NXv, x = e - y * NXv;
                float* cr = out + voxFloats + (size_t)vox * 3;
                cr[0] = 0.0f; cr[1] = (float)y; cr[2] = (float)x;
            }
            if (hasCounts) out[voxFloats + coordFloats + vox] = (float)cnt[j];
        }
        exO += occ[j];
    }
}

// K_place: per-point stable placement, 2 points per thread (two interleaved
// dependency chains double MLP at the same occupancy). lin is RECOMPUTED from
// the coalesced pts load. rank of point i = #recorded indices < i. Tail
// blocks restore the all-zero scratch invariant.
__device__ __forceinline__ void place_one(const float4* __restrict__ pts,
                                          float4* __restrict__ out4, int i) {
    float4 p = pts[i];
    int lin = bin_lin(p);
    if (lin < 0) return;
    int info = g_voxid[lin];
    int vox = info >> 8;
    int cc  = info & 255;
    if (cc > MAXP) cc = MAXP;
    int rank = 0;
    const int* __restrict__ rowA = g_slotsA + (size_t)lin * HOTS;
    int ccA = (cc < HOTS) ? cc : HOTS;
    for (int j = 0; j < ccA; j++) rank += (rowA[j] < i) ? 1 : 0;
    if (cc > HOTS) {
        const int* __restrict__ rowB = g_slotsB + (size_t)lin * (MAXP - HOTS);
        for (int j = 0; j < cc - HOTS; j++) rank += (rowB[j] < i) ? 1 : 0;
    }
    if (rank < MAXP) out4[(size_t)vox * MAXP + rank] = p;
}

__global__ void k_place(const float4* __restrict__ pts, float4* __restrict__ out4,
                        int n, int half) {
    int t = blockIdx.x * blockDim.x + threadIdx.x;
    if (t < half) {
        place_one(pts, out4, t);
        int i2 = t + half;
        if (i2 < n) place_one(pts, out4, i2);
    } else {
        int zi = t - half;
        const int q = CAPV / 4;               // 53568
        if (zi < q)           ((int4*)g_count)[zi] = make_int4(0, 0, 0, 0);
        else if (zi < q + NB) g_look[zi - q] = 0ull;
    }
}

extern "C" void kernel_launch(void* const* d_in, const int* in_sizes, int n_in,
                              void* d_out, int out_size) {
    const float4* pts = (const float4*)d_in[0];
    int n = in_sizes[0] / 4;
    if (n > NPTS_MAX) n = NPTS_MAX;

    const long long voxFloats   = (long long)CAPV * MAXP * 4;  // 85,708,800
    const long long coordFloats = (long long)CAPV * 3;         // 642,816
    const long long total = (long long)out_size;

    const int hasCoords = (total >= voxFloats + coordFloats) ? 1 : 0;
    const int hasCounts = (total >= voxFloats + coordFloats + CAPV) ? 1 : 0;

    const int T = 256;
    const int half = (n + 1) / 2;
    const int placeThreads = half + (CAPV / 4) + NB;
    const int binBlocks = (n + T * 2 - 1) / (T * 2);

    // Bulk padding via driver memset (pure-store fast path), then the coords
    // slice gets its -1.0f pattern from a tiny kernel.
    cudaMemsetAsync(d_out, 0, (size_t)total * sizeof(float), 0);
    if (hasCoords) {
        int m4 = (int)(coordFloats / 4);      // 160,704 float4s
        float* coords = (float*)d_out + voxFloats;
        k_fillc<<<(m4 + T - 1) / T, T>>>((float4*)coords, m4);
    }
    k_bin  <<<binBlocks, T>>>(pts, n);
    k_scan <<<NB, 256>>>((float*)d_out, hasCoords, hasCounts);
    k_place<<<(placeThreads + T - 1) / T, T>>>(pts, (float4*)d_out, n, half);
}

// round 17
// speedup vs baseline: 1.0857x; 1.0857x over previous
#include <cuda_runtime.h>
#include <cuda_bf16.h>

#define NXv 432
#define NYv 496
#define CAPV (NXv * NYv)            // 214272 (NZ=1)
#define MAXP 100
#define NPTS_MAX 300000
#define NB 210                      // ceil(CAPV / 1024)
#define HOTS 8                      // hot slots per voxel (L2-resident table)

// ---- scratch (zero-init at load; k_place tail restores the invariant that
// g_count / g_look are all-zero on entry). Slot tables / g_voxid need no
// cleaning: reads are always bounded by / gated on this call's data. ----
__device__ int g_count[CAPV];
__device__ int g_slotsA[CAPV * HOTS];         // hot slots: 6.9 MB -> L2-resident
__device__ int g_slotsB[CAPV * (MAXP - HOTS)];// cold overflow: ~0 traffic in practice
__device__ int g_voxid[CAPV];                 // packed: compactRow*256 + min(cnt,255)
__device__ unsigned long long g_look[NB];     // decoupled-lookback words

// Pack: bits[0:20)=occ prefix, bits[62:64)=status (1=AGG, 2=PREFIX)
__device__ __forceinline__ unsigned long long packLB(int st, int o) {
    return ((unsigned long long)st << 62) | (unsigned long long)(o & 0xFFFFF);
}

// Shared binning math. NUMERICS LOCKED (R7): XLA rewrites /const into
// *reciprocal(const); fp32(1/0.16f)=6.25f exactly. Returns -1 if invalid.
__device__ __forceinline__ int bin_lin(float4 p) {
    bool valid = (p.x >= 0.0f)    && (p.x < 69.12f) &&
                 (p.y >= -39.68f) && (p.y < 39.68f) &&
                 (p.z >= -3.0f)   && (p.z < 1.0f);
    if (!valid) return -1;
    float qx = __fmul_rn(__fsub_rn(p.x,   0.0f),  6.25f);
    float qy = __fmul_rn(__fsub_rn(p.y, -39.68f), 6.25f);
    int vx = min(max((int)floorf(qx), 0), NXv - 1);
    int vy = min(max((int)floorf(qy), 0), NYv - 1);
    return vy * NXv + vx;             // vz always 0 (NZ=1; z-range validated)
}

// ---------------------------------------------------------------
// K_fused: heterogeneous grid. Blocks [0, binBlocks) run the per-point
// binning (latency/atomic work); the remaining blocks run the pure padding
// fill (4 coalesced float4 stores/thread, no loads). Bin blocks come FIRST
// so wave 1 starts them immediately — their ~7us of latency work hides
// inside the 45us DRAM-bound fill window (stream-level overlap is dead on
// this harness, but intra-launch block concurrency is guaranteed).
__global__ void k_fused(const float4* __restrict__ pts, int n, int binBlocks,
                        float4* __restrict__ out, int n4, int cS4, int cE4) {
    if ((int)blockIdx.x < binBlocks) {
        int i0 = blockIdx.x * (blockDim.x * 2) + threadIdx.x;
#pragma unroll
        for (int k = 0; k < 2; k++) {
            int i = i0 + k * 256;
            if (i >= n) continue;
            int lin = bin_lin(pts[i]);
            if (lin < 0) continue;
            int slot = atomicAdd(&g_count[lin], 1);
            if (slot < HOTS)      g_slotsA[lin * HOTS + slot] = i;
            else if (slot < MAXP) g_slotsB[lin * (MAXP - HOTS) + slot - HOTS] = i;
        }
    } else {
        int base = (blockIdx.x - binBlocks) * (blockDim.x * 4) + threadIdx.x;
#pragma unroll
        for (int k = 0; k < 4; k++) {
            int i = base + k * 256;
            if (i < n4) {
                float v = (i >= cS4 && i < cE4) ? -1.0f : 0.0f;
                out[i] = make_float4(v, v, v, v);
            }
        }
    }
}

// K_scan: single-pass decoupled-lookback scan of the occupied flag. Packs
// {compactRow, cnt} per occupied lin, and writes coords + counts DIRECTLY to
// the output (the fused fill has already laid down the -1 / 0 padding).
__global__ void k_scan(float* __restrict__ out, int hasCoords, int hasCounts) {
    const long long voxFloats   = (long long)CAPV * MAXP * 4;
    const long long coordFloats = (long long)CAPV * 3;
    __shared__ int wO[8];
    __shared__ int sExc;
    int b = blockIdx.x, t = threadIdx.x;
    int lane = t & 31, warp = t >> 5;
    int e0 = b * 1024 + t * 4;
    int occ[4], cnt[4];
    int so = 0;
#pragma unroll
    for (int j = 0; j < 4; j++) {
        int e = e0 + j;
        int c = (e < CAPV) ? g_count[e] : 0;
        cnt[j] = c;
        occ[j] = (c > 0) ? 1 : 0;
        so += occ[j];
    }
    int io = so;
#pragma unroll
    for (int off = 1; off < 32; off <<= 1) {
        int vo = __shfl_up_sync(0xFFFFFFFFu, io, off);
        if (lane >= off) io += vo;
    }
    if (lane == 31) wO[warp] = io;
    __syncthreads();
    if (warp == 0 && lane < 8) {
        int a = wO[lane];
#pragma unroll
        for (int off = 1; off < 8; off <<= 1) {
            int va = __shfl_up_sync(0xFFu, a, off);
            if (lane >= off) a += va;
        }
        wO[lane] = a;
    }
    __syncthreads();
    int blkO = wO[7];

    // ---- decoupled lookback (warp 0) ----
    if (t < 32) {
        if (lane == 0 && b > 0)
            *(volatile unsigned long long*)(g_look + b) = packLB(1, blkO);
        int accO = 0;
        if (b > 0) {
            int end = b;
            for (;;) {
                int idx = end - 1 - lane;
                unsigned long long v = 0;
                if (idx >= 0) {
                    volatile unsigned long long* vp = g_look + idx;
                    do { v = *vp; } while ((v >> 62) == 0ull);
                }
                bool isPref = (idx >= 0) && ((v >> 62) == 2ull);
                unsigned pm = __ballot_sync(0xFFFFFFFFu, isPref);
                int o = (idx >= 0) ? (int)(v & 0xFFFFF) : 0;
                if (pm) {
                    int fp = __ffs(pm) - 1;
                    if (lane > fp) o = 0;
                }
#pragma unroll
                for (int off = 16; off; off >>= 1)
                    o += __shfl_down_sync(0xFFFFFFFFu, o, off);
                if (lane == 0) accO += o;
                if (pm) break;
                end -= 32;
            }
        }
        if (lane == 0) {
            sExc = accO;
            *(volatile unsigned long long*)(g_look + b) = packLB(2, accO + blkO);
        }
    }
    __syncthreads();

    int exO = sExc + (warp ? wO[warp - 1] : 0) + (io - so);
#pragma unroll
    for (int j = 0; j < 4; j++) {
        int e = e0 + j;
        if (e < CAPV && cnt[j] > 0) {
            int vox = exO;
            int cpk = (cnt[j] < 255) ? cnt[j] : 255;
            g_voxid[e] = vox * 256 + cpk;
            if (hasCoords) {
                int y = e / NXv, x = e - y * NXv;
                float* cr = out + voxFloats + (size_t)vox * 3;
                cr[0] = 0.0f; cr[1] = (float)y; cr[2] = (float)x;
            }
            if (hasCounts) out[voxFloats + coordFloats + vox] = (float)cnt[j];
        }
        exO += occ[j];
    }
}

// K_place: per-point stable placement (R15 form — single point per thread;
// the 2pt-ILP variant traded occupancy 1:1 and was neutral). lin RECOMPUTED
// from the coalesced pts load; rank of point i = #recorded indices < i (the
// stable-sort position, no sort). Tail restores the zero invariant.
__global__ void k_place(const float4* __restrict__ pts, float4* __restrict__ out4,
                        int n) {
    int i = blockIdx.x * blockDim.x + threadIdx.x;
    if (i < n) {
        float4 p = pts[i];
        int lin = bin_lin(p);
        if (lin < 0) return;
        int info = g_voxid[lin];
        int vox = info >> 8;
        int cc  = info & 255;
        if (cc > MAXP) cc = MAXP;
        int rank = 0;
        const int* __restrict__ rowA = g_slotsA + (size_t)lin * HOTS;
        int ccA = (cc < HOTS) ? cc : HOTS;
        for (int j = 0; j < ccA; j++) rank += (rowA[j] < i) ? 1 : 0;
        if (cc > HOTS) {
            const int* __restrict__ rowB = g_slotsB + (size_t)lin * (MAXP - HOTS);
            for (int j = 0; j < cc - HOTS; j++) rank += (rowB[j] < i) ? 1 : 0;
        }
        if (rank < MAXP) out4[(size_t)vox * MAXP + rank] = p;
    } else {
        int zi = i - n;
        const int q = CAPV / 4;               // 53568
        if (zi < q)           ((int4*)g_count)[zi] = make_int4(0, 0, 0, 0);
        else if (zi < q + NB) g_look[zi - q] = 0ull;
    }
}

extern "C" void kernel_launch(void* const* d_in, const int* in_sizes, int n_in,
                              void* d_out, int out_size) {
    const float4* pts = (const float4*)d_in[0];
    int n = in_sizes[0] / 4;
    if (n > NPTS_MAX) n = NPTS_MAX;

    const long long voxFloats   = (long long)CAPV * MAXP * 4;  // 85,708,800
    const long long coordFloats = (long long)CAPV * 3;         // 642,816
    const long long total = (long long)out_size;

    const int hasCoords = (total >= voxFloats + coordFloats) ? 1 : 0;
    const int hasCounts = (total >= voxFloats + coordFloats + CAPV) ? 1 : 0;
    const int n4  = (int)(total / 4);
    const int cS4 = hasCoords ? (int)(voxFloats / 4) : n4;
    const int cE4 = hasCoords ? (int)((voxFloats + coordFloats) / 4) : n4;

    const int T = 256;
    const int binBlocks  = (n + T * 2 - 1) / (T * 2);          // 586
    const int fillBlocks = (n4 + T * 4 - 1) / (T * 4);         // 21134
    const int placeThreads = n + (CAPV / 4) + NB;

    k_fused<<<binBlocks + fillBlocks, T>>>(pts, n, binBlocks,
                                           (float4*)d_out, n4, cS4, cE4);
    k_scan <<<NB, 256>>>((float*)d_out, hasCoords, hasCounts);
    k_place<<<(placeThreads + T - 1) / T, T>>>(pts, (float4*)d_out, n);
}